// round 6
// baseline (speedup 1.0000x reference)
#include <cuda_runtime.h>

// Embedder: multirate zero-insert upsample -> conv1d(1->256, K=5, same) -> gather.
// Closed-form per-stream FIR taps. Output = X[3,256,60000] ++ S[2,60000] (~185 MB).
//
// R6: 2 float4 per thread per d-iteration (f4 and f4+256 of the same row) ->
// weight LDS + loop overhead amortized over 2 STG.128. 838 blocks ~= 1 wave.

#define L250   15000
#define L500   30000
#define L1000  60000
#define ROW4   15000                       // float4 per (stream,d) row
#define X4TOT  (768 * ROW4)                // 11,520,000 float4
#define S4TOT  30000
#define CHUNK4 512
#define NCH    30                          // ceil(15000 / 512)
#define NDG    8                           // 8 groups of 32 d
#define DG     32
#define XBLOCKS (3 * NCH * NDG)            // 720
#define SBLOCKS ((S4TOT + 255) / 256)      // 118

__device__ __forceinline__ float ldx(const float* __restrict__ x, int i, int l) {
    return (i >= 0 && i < l) ? __ldg(x + i) : 0.0f;
}

__global__ void __launch_bounds__(256, 6)
embedder_kernel(const float* __restrict__ x250,
                const float* __restrict__ x500,
                const float* __restrict__ x1000,
                const float* __restrict__ W,   // [256,1,5]
                const float* __restrict__ b,   // [256]
                float4* __restrict__ out)
{
    int blk = blockIdx.x;

    if (blk < XBLOCKS) {
        int stream = blk / (NCH * NDG);
        int rem    = blk - stream * (NCH * NDG);
        int chunk  = rem >> 3;                 // / NDG
        int g      = rem & 7;                  // % NDG
        int t      = threadIdx.x;

        __shared__ float sw[DG][6];            // {w0,w1,w2,w3,w4,b}
        if (t < DG) {
            int d = g * DG + t;
            #pragma unroll
            for (int k = 0; k < 5; k++) sw[t][k] = __ldg(W + d * 5 + k);
            sw[t][5] = __ldg(b + d);
        }
        __syncthreads();

        int f4a = chunk * CHUNK4 + t;
        int f4b = f4a + 256;
        bool sA = f4a < ROW4, sB = f4b < ROW4;   // store guards
        if (!sA) return;

        float4* po = out + ((long)(stream * 256 + g * DG) * ROW4 + f4a);
        const float4 ZZ = make_float4(0.f, 0.f, 0.f, 0.f);

        if (stream == 0) {
            bool aA = f4a < 3750, aB = f4b < 3750;
            float4 cA = aA ? __ldg((const float4*)x250 + f4a) : ZZ;
            float4 cB = aB ? __ldg((const float4*)x250 + f4b) : ZZ;
            #pragma unroll 4
            for (int i = 0; i < DG; i++) {
                float2 cd = *(const float2*)&sw[i][2];
                float2 ef = *(const float2*)&sw[i][4];
                float w2 = cd.x, bb = ef.y;
                float4 oA = ZZ, oB = ZZ;
                if (aA) {
                    oA.x = fmaf(w2, cA.x, bb); oA.y = fmaf(w2, cA.y, bb);
                    oA.z = fmaf(w2, cA.z, bb); oA.w = fmaf(w2, cA.w, bb);
                }
                if (aB) {
                    oB.x = fmaf(w2, cB.x, bb); oB.y = fmaf(w2, cB.y, bb);
                    oB.z = fmaf(w2, cB.z, bb); oB.w = fmaf(w2, cB.w, bb);
                }
                __stcs(po, oA);
                if (sB) __stcs(po + 256, oB);
                po += ROW4;
            }
        } else if (stream == 1) {
            bool aA = f4a < 7500, aB = f4b < 7500;
            int pa = f4a * 4, pb = f4b * 4;
            float vA0 = aA ? ldx(x500, pa - 1, L500) : 0.f;
            float4 cA = aA ? __ldg((const float4*)x500 + f4a) : ZZ;
            float vA5 = aA ? ldx(x500, pa + 4, L500) : 0.f;
            float vB0 = aB ? ldx(x500, pb - 1, L500) : 0.f;
            float4 cB = aB ? __ldg((const float4*)x500 + f4b) : ZZ;
            float vB5 = aB ? ldx(x500, pb + 4, L500) : 0.f;
            #pragma unroll 4
            for (int i = 0; i < DG; i++) {
                float2 ab = *(const float2*)&sw[i][0];
                float2 cd = *(const float2*)&sw[i][2];
                float2 ef = *(const float2*)&sw[i][4];
                float w0 = ab.x, w2 = cd.x, w4 = ef.x, bb = ef.y;
                float4 oA = ZZ, oB = ZZ;
                if (aA) {
                    oA.x = fmaf(w0, vA0,  fmaf(w2, cA.x, fmaf(w4, cA.y, bb)));
                    oA.y = fmaf(w0, cA.x, fmaf(w2, cA.y, fmaf(w4, cA.z, bb)));
                    oA.z = fmaf(w0, cA.y, fmaf(w2, cA.z, fmaf(w4, cA.w, bb)));
                    oA.w = fmaf(w0, cA.z, fmaf(w2, cA.w, fmaf(w4, vA5,  bb)));
                }
                if (aB) {
                    oB.x = fmaf(w0, vB0,  fmaf(w2, cB.x, fmaf(w4, cB.y, bb)));
                    oB.y = fmaf(w0, cB.x, fmaf(w2, cB.y, fmaf(w4, cB.z, bb)));
                    oB.z = fmaf(w0, cB.y, fmaf(w2, cB.z, fmaf(w4, cB.w, bb)));
                    oB.w = fmaf(w0, cB.z, fmaf(w2, cB.w, fmaf(w4, vB5,  bb)));
                }
                __stcs(po, oA);
                if (sB) __stcs(po + 256, oB);
                po += ROW4;
            }
        } else {
            int pa = f4a * 4, pb = f4b * 4;
            float uA0 = ldx(x1000, pa - 2, L1000);
            float uA1 = ldx(x1000, pa - 1, L1000);
            float4 cA = __ldg((const float4*)x1000 + f4a);
            float uA6 = ldx(x1000, pa + 4, L1000);
            float uA7 = ldx(x1000, pa + 5, L1000);
            float uB0 = 0.f, uB1 = 0.f, uB6 = 0.f, uB7 = 0.f;
            float4 cB = ZZ;
            if (sB) {
                uB0 = ldx(x1000, pb - 2, L1000);
                uB1 = ldx(x1000, pb - 1, L1000);
                cB  = __ldg((const float4*)x1000 + f4b);
                uB6 = ldx(x1000, pb + 4, L1000);
                uB7 = ldx(x1000, pb + 5, L1000);
            }
            #pragma unroll 4
            for (int i = 0; i < DG; i++) {
                float2 ab = *(const float2*)&sw[i][0];
                float2 cd = *(const float2*)&sw[i][2];
                float2 ef = *(const float2*)&sw[i][4];
                float4 oA, oB;
                oA.x = fmaf(ab.x, uA0,  fmaf(ab.y, uA1,  fmaf(cd.x, cA.x, fmaf(cd.y, cA.y, fmaf(ef.x, cA.z, ef.y)))));
                oA.y = fmaf(ab.x, uA1,  fmaf(ab.y, cA.x, fmaf(cd.x, cA.y, fmaf(cd.y, cA.z, fmaf(ef.x, cA.w, ef.y)))));
                oA.z = fmaf(ab.x, cA.x, fmaf(ab.y, cA.y, fmaf(cd.x, cA.z, fmaf(cd.y, cA.w, fmaf(ef.x, uA6,  ef.y)))));
                oA.w = fmaf(ab.x, cA.y, fmaf(ab.y, cA.z, fmaf(cd.x, cA.w, fmaf(cd.y, uA6,  fmaf(ef.x, uA7,  ef.y)))));
                __stcs(po, oA);
                if (sB) {
                    oB.x = fmaf(ab.x, uB0,  fmaf(ab.y, uB1,  fmaf(cd.x, cB.x, fmaf(cd.y, cB.y, fmaf(ef.x, cB.z, ef.y)))));
                    oB.y = fmaf(ab.x, uB1,  fmaf(ab.y, cB.x, fmaf(cd.x, cB.y, fmaf(cd.y, cB.z, fmaf(ef.x, cB.w, ef.y)))));
                    oB.z = fmaf(ab.x, cB.x, fmaf(ab.y, cB.y, fmaf(cd.x, cB.z, fmaf(cd.y, cB.w, fmaf(ef.x, uB6,  ef.y)))));
                    oB.w = fmaf(ab.x, cB.y, fmaf(ab.y, cB.z, fmaf(cd.x, cB.w, fmaf(cd.y, uB6,  fmaf(ef.x, uB7,  ef.y)))));
                    __stcs(po + 256, oB);
                }
                po += ROW4;
            }
        }
    } else {
        // S = [rows(60000), cols(60000)] as float
        int i = (blk - XBLOCKS) * 256 + threadIdx.x;
        if (i < S4TOT) {
            int e = i * 4;
            float4 o;
            float* pf = (float*)&o;
            if (e < L1000) {
                float r = (e < L250) ? 0.f : ((e < L250 + L500) ? 1.f : 2.f);
                o = make_float4(r, r, r, r);
            } else {
                int p = e - L1000;
                #pragma unroll
                for (int k = 0; k < 4; k++) {
                    int q = p + k;
                    float cc;
                    if (q < L250)             cc = (float)(q * 4);
                    else if (q < L250 + L500) cc = (float)((q - L250) * 2);
                    else                      cc = (float)(q - (L250 + L500));
                    pf[k] = cc;
                }
            }
            __stcs(out + X4TOT + i, o);
        }
    }
}

extern "C" void kernel_launch(void* const* d_in, const int* in_sizes, int n_in,
                              void* d_out, int out_size) {
    const float* x250  = (const float*)d_in[0];
    const float* x500  = (const float*)d_in[1];
    const float* x1000 = (const float*)d_in[2];
    const float* W     = (const float*)d_in[3];
    const float* b     = (const float*)d_in[4];
    float4* out = (float4*)d_out;

    embedder_kernel<<<XBLOCKS + SBLOCKS, 256>>>(x250, x500, x1000, W, b, out);
}

// round 7
// speedup vs baseline: 1.0381x; 1.0381x over previous
#include <cuda_runtime.h>

// Embedder: multirate zero-insert upsample -> conv1d(1->256, K=5, same) -> gather.
// Closed-form FIR taps. Output = X[3,256,60000] ++ S[2,60000] (~185 MB).
//
// R7: issue-bound -> cut instructions/output with packed fma.rn.f32x2 (FFMA2).
// Shifted input-window pairs hoisted out of the d-loop; weights pre-duplicated
// (w,w) in smem so 3 broadcast LDS.128 feed FFMA2 directly. 2 positions/thread,
// 128-thread blocks keep grid at 1651 for occupancy.

#define L250   15000
#define L500   30000
#define L1000  60000
#define ROW4   15000
#define X4TOT  (768 * ROW4)                // 11,520,000 float4
#define S4TOT  30000
#define NCH    59                          // ceil(15000/256); chunk = 256 f4
#define NDG    8
#define DG     32
#define XBLOCKS (3 * NCH * NDG)            // 1416
#define SBLOCKS ((S4TOT + 127) / 128)      // 235

typedef unsigned long long u64t;

__device__ __forceinline__ u64t pk(float lo, float hi) {
    u64t r; asm("mov.b64 %0, {%1, %2};" : "=l"(r) : "f"(lo), "f"(hi)); return r;
}
__device__ __forceinline__ u64t f2(u64t a, u64t b, u64t c) {
    u64t d; asm("fma.rn.f32x2 %0, %1, %2, %3;" : "=l"(d) : "l"(a), "l"(b), "l"(c)); return d;
}
union Cvt { ulonglong2 u; float4 f; };

__device__ __forceinline__ float ldx(const float* __restrict__ x, int i, int l) {
    return (i >= 0 && i < l) ? __ldg(x + i) : 0.0f;
}

__global__ void __launch_bounds__(128)
embedder_kernel(const float* __restrict__ x250,
                const float* __restrict__ x500,
                const float* __restrict__ x1000,
                const float* __restrict__ W,   // [256,1,5]
                const float* __restrict__ b,   // [256]
                float4* __restrict__ out)
{
    int blk = blockIdx.x;

    if (blk < XBLOCKS) {
        int stream = blk / (NCH * NDG);
        int rem    = blk - stream * (NCH * NDG);
        int chunk  = rem >> 3;
        int g      = rem & 7;
        int t      = threadIdx.x;

        // weights pre-duplicated as (w,w) pairs: row = 6 float2 = 48B (16B-aligned)
        __shared__ float2 swp[DG][6];
        if (t < DG) {
            int d = g * DG + t;
            #pragma unroll
            for (int k = 0; k < 5; k++) { float w = __ldg(W + d * 5 + k); swp[t][k] = make_float2(w, w); }
            float bb = __ldg(b + d); swp[t][5] = make_float2(bb, bb);
        }
        __syncthreads();

        int f4a = chunk * 256 + t;
        int f4b = f4a + 128;
        bool sA = f4a < ROW4, sB = f4b < ROW4;
        if (!sA) return;

        float4* po = out + ((long)(stream * 256 + g * DG) * ROW4 + f4a);
        const float4 ZZ = make_float4(0.f, 0.f, 0.f, 0.f);
        const u64t Z2 = 0ull;
        const ulonglong2* wrow0 = (const ulonglong2*)&swp[0][0];  // stride 3 per d

        if (stream == 0) {
            bool aA = f4a < 3750, aB = f4b < 3750;
            float4 cA = aA ? __ldg((const float4*)x250 + f4a) : ZZ;
            float4 cB = aB ? __ldg((const float4*)x250 + f4b) : ZZ;
            u64t A01 = pk(cA.x, cA.y), A23 = pk(cA.z, cA.w);
            u64t B01 = pk(cB.x, cB.y), B23 = pk(cB.z, cB.w);
            #pragma unroll 4
            for (int i = 0; i < DG; i++) {
                ulonglong2 q1 = wrow0[i * 3 + 1];   // (w2,w2),(w3,w3)
                ulonglong2 q2 = wrow0[i * 3 + 2];   // (w4,w4),(b,b)
                u64t W2 = q1.x, BB = q2.y;
                Cvt oA, oB;
                oA.u.x = aA ? f2(W2, A01, BB) : Z2;
                oA.u.y = aA ? f2(W2, A23, BB) : Z2;
                __stcs(po, oA.f);
                if (sB) {
                    oB.u.x = aB ? f2(W2, B01, BB) : Z2;
                    oB.u.y = aB ? f2(W2, B23, BB) : Z2;
                    __stcs(po + 128, oB.f);
                }
                po += ROW4;
            }
        } else if (stream == 1) {
            bool aA = f4a < 7500, aB = f4b < 7500;
            int pa = f4a * 4, pb = f4b * 4;
            float vA0 = aA ? ldx(x500, pa - 1, L500) : 0.f;
            float4 cA = aA ? __ldg((const float4*)x500 + f4a) : ZZ;
            float vA5 = aA ? ldx(x500, pa + 4, L500) : 0.f;
            float vB0 = aB ? ldx(x500, pb - 1, L500) : 0.f;
            float4 cB = aB ? __ldg((const float4*)x500 + f4b) : ZZ;
            float vB5 = aB ? ldx(x500, pb + 4, L500) : 0.f;
            // pairs: Q0=(v0,x) Q1=(x,y) Q2=(y,z) Q3=(z,w) Q4=(w,v5)
            u64t QA0 = pk(vA0, cA.x), QA1 = pk(cA.x, cA.y), QA2 = pk(cA.y, cA.z),
                 QA3 = pk(cA.z, cA.w), QA4 = pk(cA.w, vA5);
            u64t QB0 = pk(vB0, cB.x), QB1 = pk(cB.x, cB.y), QB2 = pk(cB.y, cB.z),
                 QB3 = pk(cB.z, cB.w), QB4 = pk(cB.w, vB5);
            #pragma unroll 4
            for (int i = 0; i < DG; i++) {
                ulonglong2 q0 = wrow0[i * 3 + 0];   // (w0,w0),(w1,w1)
                ulonglong2 q2 = wrow0[i * 3 + 2];   // (w4,w4),(b,b)
                u64t W0 = q0.x, BB = q2.y, W4 = q2.x;
                u64t W2 = ((const u64t*)&swp[i][2])[0];
                Cvt oA, oB;
                oA.u.x = aA ? f2(W0, QA0, f2(W2, QA1, f2(W4, QA2, BB))) : Z2;
                oA.u.y = aA ? f2(W0, QA2, f2(W2, QA3, f2(W4, QA4, BB))) : Z2;
                __stcs(po, oA.f);
                if (sB) {
                    oB.u.x = aB ? f2(W0, QB0, f2(W2, QB1, f2(W4, QB2, BB))) : Z2;
                    oB.u.y = aB ? f2(W0, QB2, f2(W2, QB3, f2(W4, QB4, BB))) : Z2;
                    __stcs(po + 128, oB.f);
                }
                po += ROW4;
            }
        } else {
            int pa = f4a * 4, pb = f4b * 4;
            float uA0 = ldx(x1000, pa - 2, L1000);
            float uA1 = ldx(x1000, pa - 1, L1000);
            float4 cA = __ldg((const float4*)x1000 + f4a);
            float uA6 = ldx(x1000, pa + 4, L1000);
            float uA7 = ldx(x1000, pa + 5, L1000);
            float uB0 = 0.f, uB1 = 0.f, uB6 = 0.f, uB7 = 0.f;
            float4 cB = ZZ;
            if (sB) {
                uB0 = ldx(x1000, pb - 2, L1000);
                uB1 = ldx(x1000, pb - 1, L1000);
                cB  = __ldg((const float4*)x1000 + f4b);
                uB6 = ldx(x1000, pb + 4, L1000);
                uB7 = ldx(x1000, pb + 5, L1000);
            }
            // pairs: P0=(u0,u1) P1=(u1,x) P2=(x,y) P3=(y,z) P4=(z,w) P5=(w,u6) P6=(u6,u7)
            u64t PA0 = pk(uA0, uA1), PA1 = pk(uA1, cA.x), PA2 = pk(cA.x, cA.y),
                 PA3 = pk(cA.y, cA.z), PA4 = pk(cA.z, cA.w), PA5 = pk(cA.w, uA6),
                 PA6 = pk(uA6, uA7);
            u64t PB0 = pk(uB0, uB1), PB1 = pk(uB1, cB.x), PB2 = pk(cB.x, cB.y),
                 PB3 = pk(cB.y, cB.z), PB4 = pk(cB.z, cB.w), PB5 = pk(cB.w, uB6),
                 PB6 = pk(uB6, uB7);
            #pragma unroll 4
            for (int i = 0; i < DG; i++) {
                ulonglong2 q0 = wrow0[i * 3 + 0];   // W0, W1
                ulonglong2 q1 = wrow0[i * 3 + 1];   // W2, W3
                ulonglong2 q2 = wrow0[i * 3 + 2];   // W4, BB
                u64t W0 = q0.x, W1 = q0.y, W2 = q1.x, W3 = q1.y, W4 = q2.x, BB = q2.y;
                Cvt oA;
                oA.u.x = f2(W0, PA0, f2(W1, PA1, f2(W2, PA2, f2(W3, PA3, f2(W4, PA4, BB)))));
                oA.u.y = f2(W0, PA2, f2(W1, PA3, f2(W2, PA4, f2(W3, PA5, f2(W4, PA6, BB)))));
                __stcs(po, oA.f);
                if (sB) {
                    Cvt oB;
                    oB.u.x = f2(W0, PB0, f2(W1, PB1, f2(W2, PB2, f2(W3, PB3, f2(W4, PB4, BB)))));
                    oB.u.y = f2(W0, PB2, f2(W1, PB3, f2(W2, PB4, f2(W3, PB5, f2(W4, PB6, BB)))));
                    __stcs(po + 128, oB.f);
                }
                po += ROW4;
            }
        }
    } else {
        // S = [rows(60000), cols(60000)] as float
        int i = (blk - XBLOCKS) * 128 + threadIdx.x;
        if (i < S4TOT) {
            int e = i * 4;
            float4 o;
            float* pf = (float*)&o;
            if (e < L1000) {
                float r = (e < L250) ? 0.f : ((e < L250 + L500) ? 1.f : 2.f);
                o = make_float4(r, r, r, r);
            } else {
                int p = e - L1000;
                #pragma unroll
                for (int k = 0; k < 4; k++) {
                    int q = p + k;
                    float cc;
                    if (q < L250)             cc = (float)(q * 4);
                    else if (q < L250 + L500) cc = (float)((q - L250) * 2);
                    else                      cc = (float)(q - (L250 + L500));
                    pf[k] = cc;
                }
            }
            __stcs(out + X4TOT + i, o);
        }
    }
}

extern "C" void kernel_launch(void* const* d_in, const int* in_sizes, int n_in,
                              void* d_out, int out_size) {
    const float* x250  = (const float*)d_in[0];
    const float* x500  = (const float*)d_in[1];
    const float* x1000 = (const float*)d_in[2];
    const float* W     = (const float*)d_in[3];
    const float* b     = (const float*)d_in[4];
    float4* out = (float4*)d_out;

    embedder_kernel<<<XBLOCKS + SBLOCKS, 128>>>(x250, x500, x1000, W, b, out);
}